// round 10
// baseline (speedup 1.0000x reference)
#include <cuda_runtime.h>
#include <cstdint>

#define NN       8192
#define THREADS  896                 // 28 warps per block
#define BWARPS   28
#define SCAN_T   512                 // threads used for the cb block scan
#define GBLOCKS  148                 // 1 block per SM, single wave

__device__ float g_zero = 0.0f;

// ---------------------------------------------------------------------------
// One row per WARP. Each warp streams its row in 16 chunks of 512 elements
// (16 per lane), maintaining a running prefix via warp scan + lane-31
// broadcast. No block barriers in the main loop. cb = cumsum(bary) is built
// once per block into shared memory.
// ---------------------------------------------------------------------------
__global__ void __launch_bounds__(THREADS, 1)
row_w1_kernel(const float* __restrict__ x, const float* __restrict__ bary,
              float* __restrict__ out, int D, int RW)
{
    __shared__ __align__(16) float cb[NN];
    __shared__ float ws[SCAN_T / 32];

    const int t    = threadIdx.x;
    const int lane = t & 31;
    const int wid  = t >> 5;

    // ---- build cb in smem: threads 0..511, 16 elements each ----
    float4 q0, q1, q2, q3;
    float p00,p01,p02,p03,p04,p05,p06,p07,p08,p09,p10,p11,p12,p13,p14,p15;
    float s = 0.0f;
    if (t < SCAN_T) {
        const float4* bp = reinterpret_cast<const float4*>(bary) + t * 4;
        q0 = bp[0]; q1 = bp[1]; q2 = bp[2]; q3 = bp[3];

        p00 = q0.x;
        p01 = p00 + q0.y;
        p02 = p01 + q0.z;
        p03 = p02 + q0.w;
        p04 = p03 + q1.x;
        p05 = p04 + q1.y;
        p06 = p05 + q1.z;
        p07 = p06 + q1.w;
        p08 = p07 + q2.x;
        p09 = p08 + q2.y;
        p10 = p09 + q2.z;
        p11 = p10 + q2.w;
        p12 = p11 + q3.x;
        p13 = p12 + q3.y;
        p14 = p13 + q3.z;
        p15 = p14 + q3.w;

        s = p15;
        #pragma unroll
        for (int o = 1; o < 32; o <<= 1) {
            float y = __shfl_up_sync(0xFFFFFFFFu, s, o);
            if (lane >= o) s += y;
        }
        if (lane == 31) ws[wid] = s;
    }
    __syncthreads();
    if (t < SCAN_T) {
        float w = (lane < SCAN_T / 32) ? ws[lane] : 0.0f;
        #pragma unroll
        for (int o = 1; o < SCAN_T / 32; o <<= 1) {
            float y = __shfl_up_sync(0xFFFFFFFFu, w, o);
            if (lane >= o) w += y;
        }
        float woff = (wid > 0) ? __shfl_sync(0xFFFFFFFFu, w, wid - 1) : 0.0f;
        float off = woff + (s - p15);

        float* c = cb + t * 16;
        c[0]  = off + p00;  c[1]  = off + p01;  c[2]  = off + p02;  c[3]  = off + p03;
        c[4]  = off + p04;  c[5]  = off + p05;  c[6]  = off + p06;  c[7]  = off + p07;
        c[8]  = off + p08;  c[9]  = off + p09;  c[10] = off + p10;  c[11] = off + p11;
        c[12] = off + p12;  c[13] = off + p13;  c[14] = off + p14;  c[15] = off + p15;
    }
    // block 0 also writes bary into out[1..N]
    if (blockIdx.x == 0) {
        for (int i = t; i < NN; i += THREADS)
            out[1 + i] = bary[i];
    }
    __syncthreads();

    // ---- main: one row per warp, zero block barriers ----
    const int row = blockIdx.x * RW + wid;
    if (wid < RW && row < D) {
        const float4* p =
            reinterpret_cast<const float4*>(x + (size_t)row * NN);
        const float4* cbp = reinterpret_cast<const float4*>(cb);

        // chunk c, lane l: float4 indices c*128 + l*4 .. +3
        float4 v0, v1, v2, v3, n0, n1, n2, n3;
        {
            const float4* pl = p + lane * 4;
            v0 = pl[0]; v1 = pl[1]; v2 = pl[2]; v3 = pl[3];
        }

        float offset = 0.0f;
        float acc    = 0.0f;

        #pragma unroll 1
        for (int c = 0; c < 16; ++c) {
            // depth-1 prefetch of next chunk
            if (c < 15) {
                const float4* pn = p + (c + 1) * 128 + lane * 4;
                n0 = pn[0]; n1 = pn[1]; n2 = pn[2]; n3 = pn[3];
            }

            // in-lane inclusive scan of 16 elements
            float l00 = v0.x;
            float l01 = l00 + v0.y;
            float l02 = l01 + v0.z;
            float l03 = l02 + v0.w;
            float l04 = l03 + v1.x;
            float l05 = l04 + v1.y;
            float l06 = l05 + v1.z;
            float l07 = l06 + v1.w;
            float l08 = l07 + v2.x;
            float l09 = l08 + v2.y;
            float l10 = l09 + v2.z;
            float l11 = l10 + v2.w;
            float l12 = l11 + v3.x;
            float l13 = l12 + v3.y;
            float l14 = l13 + v3.z;
            float l15 = l14 + v3.w;

            // warp inclusive scan of lane totals
            float sc = l15;
            #pragma unroll
            for (int o = 1; o < 32; o <<= 1) {
                float y = __shfl_up_sync(0xFFFFFFFFu, sc, o);
                if (lane >= o) sc += y;
            }
            float lexc = sc - l15;                       // exclusive lane prefix
            float ctot = __shfl_sync(0xFFFFFFFFu, sc, 31);
            float base = offset + lexc;

            // cb chunk from smem (conflict-free LDS.128)
            const float4* cq = cbp + c * 128 + lane * 4;
            float4 c0 = cq[0], c1 = cq[1], c2 = cq[2], c3 = cq[3];

            acc += fabsf(base + l00 - c0.x);
            acc += fabsf(base + l01 - c0.y);
            acc += fabsf(base + l02 - c0.z);
            acc += fabsf(base + l03 - c0.w);
            acc += fabsf(base + l04 - c1.x);
            acc += fabsf(base + l05 - c1.y);
            acc += fabsf(base + l06 - c1.z);
            acc += fabsf(base + l07 - c1.w);
            acc += fabsf(base + l08 - c2.x);
            acc += fabsf(base + l09 - c2.y);
            acc += fabsf(base + l10 - c2.z);
            acc += fabsf(base + l11 - c2.w);
            acc += fabsf(base + l12 - c3.x);
            acc += fabsf(base + l13 - c3.y);
            acc += fabsf(base + l14 - c3.z);
            if (!(c == 15 && lane == 31))                // exclude element N-1
                acc += fabsf(base + l15 - c3.w);

            offset += ctot;
            v0 = n0; v1 = n1; v2 = n2; v3 = n3;
        }

        // warp reduction + one atomic per warp
        #pragma unroll
        for (int o = 16; o > 0; o >>= 1)
            acc += __shfl_down_sync(0xFFFFFFFFu, acc, o);
        if (lane == 0)
            atomicAdd(out, acc);
    }
}

// ---------------------------------------------------------------------------
extern "C" void kernel_launch(void* const* d_in, const int* in_sizes, int n_in,
                              void* d_out, int out_size)
{
    const float* x    = (const float*)d_in[0];   // [D, N] f32
    const float* bary = (const float*)d_in[1];   // [N] f32
    float* out = (float*)d_out;

    const int N = in_sizes[1];
    const int D = in_sizes[0] / N;
    (void)n_in; (void)out_size; (void)N;

    // out[0] = 0 via tiny D2D copy (stream-ordered before the kernel's atomics)
    void* zp = nullptr;
    cudaGetSymbolAddress(&zp, g_zero);
    cudaMemcpyAsync(out, zp, sizeof(float), cudaMemcpyDeviceToDevice, 0);

    const int grid = GBLOCKS;
    const int rw   = (D + grid - 1) / grid;      // rows per block (<= BWARPS)
    row_w1_kernel<<<grid, THREADS>>>(x, bary, out, D, rw);
}

// round 12
// speedup vs baseline: 1.4382x; 1.4382x over previous
#include <cuda_runtime.h>
#include <cstdint>

#define NN       8192
#define THREADS  896                 // 28 warps per block
#define BWARPS   28
#define SCAN_T   512                 // threads used for the cb block scan
#define GBLOCKS  148                 // 1 block per SM, single wave

__device__ float g_zero = 0.0f;

// ---------------------------------------------------------------------------
// One row per WARP, fully coalesced loads. Each warp streams its row in 16
// chunks of 512 elements; within a chunk, lane l owns float4s at indices
// {0,32,64,96}+l (each LDG.128 is 512B contiguous = 4 sectors). Four
// sub-block warp scans run simultaneously (independent shuffle chains).
// No block barriers in the main loop. cb = cumsum(bary) lives in smem.
// ---------------------------------------------------------------------------
__global__ void __launch_bounds__(THREADS, 1)
row_w1_kernel(const float* __restrict__ x, const float* __restrict__ bary,
              float* __restrict__ out, int D, int RW)
{
    __shared__ __align__(16) float cb[NN];
    __shared__ float ws[SCAN_T / 32];

    const int t    = threadIdx.x;
    const int lane = t & 31;
    const int wid  = t >> 5;

    // ---- build cb in smem: threads 0..511, 16 elements each ----
    float4 q0, q1, q2, q3;
    float p00,p01,p02,p03,p04,p05,p06,p07,p08,p09,p10,p11,p12,p13,p14,p15;
    float s = 0.0f;
    if (t < SCAN_T) {
        const float4* bp = reinterpret_cast<const float4*>(bary) + t * 4;
        q0 = bp[0]; q1 = bp[1]; q2 = bp[2]; q3 = bp[3];

        p00 = q0.x;
        p01 = p00 + q0.y;
        p02 = p01 + q0.z;
        p03 = p02 + q0.w;
        p04 = p03 + q1.x;
        p05 = p04 + q1.y;
        p06 = p05 + q1.z;
        p07 = p06 + q1.w;
        p08 = p07 + q2.x;
        p09 = p08 + q2.y;
        p10 = p09 + q2.z;
        p11 = p10 + q2.w;
        p12 = p11 + q3.x;
        p13 = p12 + q3.y;
        p14 = p13 + q3.z;
        p15 = p14 + q3.w;

        s = p15;
        #pragma unroll
        for (int o = 1; o < 32; o <<= 1) {
            float y = __shfl_up_sync(0xFFFFFFFFu, s, o);
            if (lane >= o) s += y;
        }
        if (lane == 31) ws[wid] = s;
    }
    __syncthreads();
    if (t < SCAN_T) {
        float w = (lane < SCAN_T / 32) ? ws[lane] : 0.0f;
        #pragma unroll
        for (int o = 1; o < SCAN_T / 32; o <<= 1) {
            float y = __shfl_up_sync(0xFFFFFFFFu, w, o);
            if (lane >= o) w += y;
        }
        float woff = (wid > 0) ? __shfl_sync(0xFFFFFFFFu, w, wid - 1) : 0.0f;
        float off = woff + (s - p15);

        float* c = cb + t * 16;
        c[0]  = off + p00;  c[1]  = off + p01;  c[2]  = off + p02;  c[3]  = off + p03;
        c[4]  = off + p04;  c[5]  = off + p05;  c[6]  = off + p06;  c[7]  = off + p07;
        c[8]  = off + p08;  c[9]  = off + p09;  c[10] = off + p10;  c[11] = off + p11;
        c[12] = off + p12;  c[13] = off + p13;  c[14] = off + p14;  c[15] = off + p15;
    }
    // block 0 also writes bary into out[1..N]
    if (blockIdx.x == 0) {
        for (int i = t; i < NN; i += THREADS)
            out[1 + i] = bary[i];
    }
    __syncthreads();

    // ---- main: one row per warp, zero block barriers, coalesced loads ----
    const int row = blockIdx.x * RW + wid;
    if (wid < RW && row < D) {
        const float4* p =
            reinterpret_cast<const float4*>(x + (size_t)row * NN) + lane;
        const float4* cq = reinterpret_cast<const float4*>(cb) + lane;

        // prologue: chunk 0 (each load 512B contiguous across the warp)
        float4 v0 = p[0], v1 = p[32], v2 = p[64], v3 = p[96];
        float4 n0, n1, n2, n3;

        float offset = 0.0f;
        float acc    = 0.0f;

        #pragma unroll 1
        for (int c = 0; c < 16; ++c) {
            // depth-1 prefetch of next chunk
            if (c < 15) {
                const float4* pn = p + (c + 1) * 128;
                n0 = pn[0]; n1 = pn[32]; n2 = pn[64]; n3 = pn[96];
            }

            // in-lane inclusive scans of each sub-block's 4 elements
            float a0 = v0.x, a1 = a0 + v0.y, a2 = a1 + v0.z, a3 = a2 + v0.w;
            float b0 = v1.x, b1 = b0 + v1.y, b2 = b1 + v1.z, b3 = b2 + v1.w;
            float d0 = v2.x, d1 = d0 + v2.y, d2 = d1 + v2.z, d3 = d2 + v2.w;
            float e0 = v3.x, e1 = e0 + v3.y, e2 = e1 + v3.z, e3 = e2 + v3.w;

            // four simultaneous warp inclusive scans of lane sums
            float sA = a3, sB = b3, sD = d3, sE = e3;
            #pragma unroll
            for (int o = 1; o < 32; o <<= 1) {
                float yA = __shfl_up_sync(0xFFFFFFFFu, sA, o);
                float yB = __shfl_up_sync(0xFFFFFFFFu, sB, o);
                float yD = __shfl_up_sync(0xFFFFFFFFu, sD, o);
                float yE = __shfl_up_sync(0xFFFFFFFFu, sE, o);
                if (lane >= o) { sA += yA; sB += yB; sD += yD; sE += yE; }
            }
            float TA = __shfl_sync(0xFFFFFFFFu, sA, 31);
            float TB = __shfl_sync(0xFFFFFFFFu, sB, 31);
            float TD = __shfl_sync(0xFFFFFFFFu, sD, 31);

            float baseA = offset + (sA - a3);
            float baseB = offset + TA + (sB - b3);
            float baseD = offset + TA + TB + (sD - d3);
            float baseE = offset + TA + TB + TD + (sE - e3);

            // cb for this chunk (coalesced LDS.128)
            const float4* cc = cq + c * 128;
            float4 c0 = cc[0], c1 = cc[32], c2 = cc[64], c3 = cc[96];

            acc += fabsf(baseA + a0 - c0.x);
            acc += fabsf(baseA + a1 - c0.y);
            acc += fabsf(baseA + a2 - c0.z);
            acc += fabsf(baseA + a3 - c0.w);
            acc += fabsf(baseB + b0 - c1.x);
            acc += fabsf(baseB + b1 - c1.y);
            acc += fabsf(baseB + b2 - c1.z);
            acc += fabsf(baseB + b3 - c1.w);
            acc += fabsf(baseD + d0 - c2.x);
            acc += fabsf(baseD + d1 - c2.y);
            acc += fabsf(baseD + d2 - c2.z);
            acc += fabsf(baseD + d3 - c2.w);
            acc += fabsf(baseE + e0 - c3.x);
            acc += fabsf(baseE + e1 - c3.y);
            acc += fabsf(baseE + e2 - c3.z);
            if (!(c == 15 && lane == 31))      // exclude global element N-1
                acc += fabsf(baseE + e3 - c3.w);

            offset = offset + TA + TB + TD + __shfl_sync(0xFFFFFFFFu, sE, 31);
            v0 = n0; v1 = n1; v2 = n2; v3 = n3;
        }

        // warp reduction + one atomic per warp
        #pragma unroll
        for (int o = 16; o > 0; o >>= 1)
            acc += __shfl_down_sync(0xFFFFFFFFu, acc, o);
        if (lane == 0)
            atomicAdd(out, acc);
    }
}

// ---------------------------------------------------------------------------
extern "C" void kernel_launch(void* const* d_in, const int* in_sizes, int n_in,
                              void* d_out, int out_size)
{
    const float* x    = (const float*)d_in[0];   // [D, N] f32
    const float* bary = (const float*)d_in[1];   // [N] f32
    float* out = (float*)d_out;

    const int N = in_sizes[1];
    const int D = in_sizes[0] / N;
    (void)n_in; (void)out_size; (void)N;

    // out[0] = 0 via tiny D2D copy (stream-ordered before the kernel's atomics)
    void* zp = nullptr;
    cudaGetSymbolAddress(&zp, g_zero);
    cudaMemcpyAsync(out, zp, sizeof(float), cudaMemcpyDeviceToDevice, 0);

    const int grid = GBLOCKS;
    const int rw   = (D + grid - 1) / grid;      // rows per block (<= BWARPS)
    row_w1_kernel<<<grid, THREADS>>>(x, bary, out, D, rw);
}

// round 13
// speedup vs baseline: 1.4651x; 1.0187x over previous
#include <cuda_runtime.h>
#include <cstdint>

#define NN       8192
#define THREADS  896                 // 28 warps per block
#define SCAN_T   512                 // threads used for the cb block scan
#define GBLOCKS  148                 // 1 block per SM, single wave

__device__ float g_zero = 0.0f;

// ---------------------------------------------------------------------------
// One row per WARP, fully coalesced loads. 16 chunks of 512 elements; lane l
// owns float4s {0,32,64,96}+l (each LDG.128 = 512B contiguous). Four
// interleaved warp scans per chunk; 4 independent accumulators; chunk loop
// unrolled x2 so chunk c+1's scans overlap chunk c's accumulate phase
// (running offset is the only serial carry). Zero block barriers in the
// main loop; cb = cumsum(bary) in smem.
// ---------------------------------------------------------------------------
__global__ void __launch_bounds__(THREADS, 1)
row_w1_kernel(const float* __restrict__ x, const float* __restrict__ bary,
              float* __restrict__ out, int D, int RW)
{
    __shared__ __align__(16) float cb[NN];
    __shared__ float ws[SCAN_T / 32];

    const int t    = threadIdx.x;
    const int lane = t & 31;
    const int wid  = t >> 5;

    // ---- build cb in smem: threads 0..511, 16 elements each ----
    float4 q0, q1, q2, q3;
    float p00,p01,p02,p03,p04,p05,p06,p07,p08,p09,p10,p11,p12,p13,p14,p15;
    float s = 0.0f;
    if (t < SCAN_T) {
        const float4* bp = reinterpret_cast<const float4*>(bary) + t * 4;
        q0 = bp[0]; q1 = bp[1]; q2 = bp[2]; q3 = bp[3];

        p00 = q0.x;
        p01 = p00 + q0.y;
        p02 = p01 + q0.z;
        p03 = p02 + q0.w;
        p04 = p03 + q1.x;
        p05 = p04 + q1.y;
        p06 = p05 + q1.z;
        p07 = p06 + q1.w;
        p08 = p07 + q2.x;
        p09 = p08 + q2.y;
        p10 = p09 + q2.z;
        p11 = p10 + q2.w;
        p12 = p11 + q3.x;
        p13 = p12 + q3.y;
        p14 = p13 + q3.z;
        p15 = p14 + q3.w;

        s = p15;
        #pragma unroll
        for (int o = 1; o < 32; o <<= 1) {
            float y = __shfl_up_sync(0xFFFFFFFFu, s, o);
            if (lane >= o) s += y;
        }
        if (lane == 31) ws[wid] = s;
    }
    __syncthreads();
    if (t < SCAN_T) {
        float w = (lane < SCAN_T / 32) ? ws[lane] : 0.0f;
        #pragma unroll
        for (int o = 1; o < SCAN_T / 32; o <<= 1) {
            float y = __shfl_up_sync(0xFFFFFFFFu, w, o);
            if (lane >= o) w += y;
        }
        float woff = (wid > 0) ? __shfl_sync(0xFFFFFFFFu, w, wid - 1) : 0.0f;
        float off = woff + (s - p15);

        float* c = cb + t * 16;
        c[0]  = off + p00;  c[1]  = off + p01;  c[2]  = off + p02;  c[3]  = off + p03;
        c[4]  = off + p04;  c[5]  = off + p05;  c[6]  = off + p06;  c[7]  = off + p07;
        c[8]  = off + p08;  c[9]  = off + p09;  c[10] = off + p10;  c[11] = off + p11;
        c[12] = off + p12;  c[13] = off + p13;  c[14] = off + p14;  c[15] = off + p15;
    }
    // block 0 also writes bary into out[1..N]
    if (blockIdx.x == 0) {
        for (int i = t; i < NN; i += THREADS)
            out[1 + i] = bary[i];
    }
    __syncthreads();

    // ---- main: one row per warp, zero block barriers, coalesced loads ----
    const int row = blockIdx.x * RW + wid;
    if (wid < RW && row < D) {
        const float4* p =
            reinterpret_cast<const float4*>(x + (size_t)row * NN) + lane;
        const float4* cc = reinterpret_cast<const float4*>(cb) + lane;

        // prologue: chunk 0
        float4 v0 = p[0], v1 = p[32], v2 = p[64], v3 = p[96];
        float4 n0, n1, n2, n3;

        float offset = 0.0f;
        float acc0 = 0.0f, acc1 = 0.0f, acc2 = 0.0f, acc3 = 0.0f;

        #pragma unroll 2
        for (int c = 0; c < 16; ++c) {
            // depth-1 prefetch of next chunk (pointer-bumped)
            if (c < 15) {
                const float4* pn = p + 128;
                n0 = pn[0]; n1 = pn[32]; n2 = pn[64]; n3 = pn[96];
            }

            // in-lane inclusive scans of each sub-block's 4 elements
            float a0 = v0.x, a1 = a0 + v0.y, a2 = a1 + v0.z, a3 = a2 + v0.w;
            float b0 = v1.x, b1 = b0 + v1.y, b2 = b1 + v1.z, b3 = b2 + v1.w;
            float d0 = v2.x, d1 = d0 + v2.y, d2 = d1 + v2.z, d3 = d2 + v2.w;
            float e0 = v3.x, e1 = e0 + v3.y, e2 = e1 + v3.z, e3 = e2 + v3.w;

            // four simultaneous warp inclusive scans of lane sums
            float sA = a3, sB = b3, sD = d3, sE = e3;
            #pragma unroll
            for (int o = 1; o < 32; o <<= 1) {
                float yA = __shfl_up_sync(0xFFFFFFFFu, sA, o);
                float yB = __shfl_up_sync(0xFFFFFFFFu, sB, o);
                float yD = __shfl_up_sync(0xFFFFFFFFu, sD, o);
                float yE = __shfl_up_sync(0xFFFFFFFFu, sE, o);
                if (lane >= o) { sA += yA; sB += yB; sD += yD; sE += yE; }
            }
            float TA = __shfl_sync(0xFFFFFFFFu, sA, 31);
            float TB = __shfl_sync(0xFFFFFFFFu, sB, 31);
            float TD = __shfl_sync(0xFFFFFFFFu, sD, 31);
            float TE = __shfl_sync(0xFFFFFFFFu, sE, 31);

            float baseA = offset + (sA - a3);
            float baseB = offset + TA + (sB - b3);
            float baseD = offset + TA + TB + (sD - d3);
            float baseE = offset + TA + TB + TD + (sE - e3);

            // cb for this chunk (coalesced LDS.128, pointer-bumped)
            float4 c0 = cc[0], c1 = cc[32], c2 = cc[64], c3 = cc[96];

            // four independent accumulation chains
            acc0 += fabsf(baseA + a0 - c0.x);
            acc0 += fabsf(baseA + a1 - c0.y);
            acc0 += fabsf(baseA + a2 - c0.z);
            acc0 += fabsf(baseA + a3 - c0.w);
            acc1 += fabsf(baseB + b0 - c1.x);
            acc1 += fabsf(baseB + b1 - c1.y);
            acc1 += fabsf(baseB + b2 - c1.z);
            acc1 += fabsf(baseB + b3 - c1.w);
            acc2 += fabsf(baseD + d0 - c2.x);
            acc2 += fabsf(baseD + d1 - c2.y);
            acc2 += fabsf(baseD + d2 - c2.z);
            acc2 += fabsf(baseD + d3 - c2.w);
            acc3 += fabsf(baseE + e0 - c3.x);
            acc3 += fabsf(baseE + e1 - c3.y);
            acc3 += fabsf(baseE + e2 - c3.z);
            if (!(c == 15 && lane == 31))      // exclude global element N-1
                acc3 += fabsf(baseE + e3 - c3.w);

            offset = offset + TA + TB + TD + TE;
            v0 = n0; v1 = n1; v2 = n2; v3 = n3;
            p  += 128;
            cc += 128;
        }

        float acc = (acc0 + acc1) + (acc2 + acc3);

        // warp reduction + one atomic per warp
        #pragma unroll
        for (int o = 16; o > 0; o >>= 1)
            acc += __shfl_down_sync(0xFFFFFFFFu, acc, o);
        if (lane == 0)
            atomicAdd(out, acc);
    }
}

// ---------------------------------------------------------------------------
extern "C" void kernel_launch(void* const* d_in, const int* in_sizes, int n_in,
                              void* d_out, int out_size)
{
    const float* x    = (const float*)d_in[0];   // [D, N] f32
    const float* bary = (const float*)d_in[1];   // [N] f32
    float* out = (float*)d_out;

    const int N = in_sizes[1];
    const int D = in_sizes[0] / N;
    (void)n_in; (void)out_size; (void)N;

    // out[0] = 0 via tiny D2D copy (stream-ordered before the kernel's atomics)
    void* zp = nullptr;
    cudaGetSymbolAddress(&zp, g_zero);
    cudaMemcpyAsync(out, zp, sizeof(float), cudaMemcpyDeviceToDevice, 0);

    const int grid = GBLOCKS;
    const int rw   = (D + grid - 1) / grid;      // rows per block (<= 28)
    row_w1_kernel<<<grid, THREADS>>>(x, bary, out, D, rw);
}